// round 4
// baseline (speedup 1.0000x reference)
#include <cuda_runtime.h>
#include <cstdint>

// Problem constants
#define M_SUB   8
#define N_E     1024
#define E_DIM   64
#define BS_     16
#define CC_     512
#define HH_     32
#define WW_     32
#define HW_     (HH_*WW_)          // 1024
#define NPOS    (BS_*HW_)          // 16384

// Output layout (float32):
//   [0, 8388608)                      z_vq  [bs,c,h,w]
//   [8388608]                         loss
//   [8388609, 8388609+131072)         min_encoding_indices (m-major)
//   [8519681, 8519681+1024)           bin_count
#define OFF_ZVQ  0
#define OFF_LOSS 8388608
#define OFF_IDX  8388609
#define OFF_BIN  8519681

// Scratch (device globals; no allocation allowed)
__device__ float  g_esq[M_SUB * N_E];
__device__ int    g_idx[M_SUB * NPOS];
__device__ double g_part[8192];

// ---------------- f32x2 packed FMA helpers (bit-identical per-lane fp32 FMA) ----
__device__ __forceinline__ unsigned long long pk2(float lo, float hi) {
    unsigned long long r;
    asm("mov.b64 %0, {%1, %2};" : "=l"(r) : "f"(lo), "f"(hi));
    return r;
}
__device__ __forceinline__ void upk2(unsigned long long v, float& lo, float& hi) {
    asm("mov.b64 {%0, %1}, %2;" : "=f"(lo), "=f"(hi) : "l"(v));
}
__device__ __forceinline__ unsigned long long fma2(unsigned long long a,
                                                   unsigned long long b,
                                                   unsigned long long c) {
    unsigned long long d;
    asm("fma.rn.f32x2 %0, %1, %2, %3;" : "=l"(d) : "l"(a), "l"(b), "l"(c));
    return d;
}

// ---------------- K0: zero bins --------------------------------------------
__global__ void pq_init_kernel(float* __restrict__ outBins) {
    int t = threadIdx.x;
    if (t < N_E) outBins[t] = 0.0f;
}

// ---------------- K_esq: per-code squared norms (mul then add, sequential) --
__global__ void pq_esq_kernel(const float* __restrict__ cbk) {
    int t = blockIdx.x * blockDim.x + threadIdx.x;   // 0..8191
    if (t >= M_SUB * N_E) return;
    const float* p = cbk + (size_t)t * E_DIM;
    float s = 0.0f;
    #pragma unroll
    for (int d = 0; d < E_DIM; d++) {
        float v = p[d];
        s = __fadd_rn(s, __fmul_rn(v, v));
    }
    g_esq[t] = s;
}

// ---------------- K1: distances + argmin ------------------------------------
// Block: 256 threads (16x16). Tile: 128 rows x all 1024 codes (8 chunks of 128).
// grid = (128 row-tiles, 8 sub-codebooks)
#define TN   128
#define TC   128
#define CBS  132   // padded smem stride for transposed codebook chunk

__global__ void __launch_bounds__(256, 2)
pq_dist_kernel(const float* __restrict__ z,
               const float* __restrict__ cbk,
               float* __restrict__ outIdx,
               float* __restrict__ outBins)
{
    extern __shared__ float sm[];
    float* szt  = sm;                       // 64*128   = 8192 floats (z tile, k-major)
    float* scb  = sm + 8192;                // 64*132   = 8448 floats (codebook chunk, k-major)
    float* sesq = sm + 8192 + 8448;         // 1024
    float* szsq = sesq + 1024;              // 128

    const int m  = blockIdx.y;
    const int n0 = blockIdx.x * TN;         // first row of tile
    const int b  = n0 >> 10;                // n = b*1024 + p, tile inside one b
    const int p0 = n0 & 1023;
    const int tid = threadIdx.x;
    const int tx = tid & 15, ty = tid >> 4;

    // Load z tile: channels [m*64, m*64+64), positions [p0, p0+128)
    const float* zbase = z + ((size_t)(b * CC_ + m * E_DIM) * HW_) + p0;
    #pragma unroll
    for (int it = 0; it < 8; it++) {
        int i = tid + it * 256;             // 0..2047 float4 slots
        int d = i >> 5, j4 = i & 31;
        float4 v = *(const float4*)(zbase + (size_t)d * HW_ + j4 * 4);
        *(float4*)(szt + d * TN + j4 * 4) = v;
    }
    // esq for this sub-codebook
    #pragma unroll
    for (int it = 0; it < 4; it++)
        sesq[tid + it * 256] = g_esq[m * N_E + tid + it * 256];
    __syncthreads();

    // per-row ||z||^2 : square rounded, then sequential add (mimics zf**2 .sum)
    if (tid < TN) {
        float s = 0.0f;
        #pragma unroll
        for (int k = 0; k < E_DIM; k++) {
            float v = szt[k * TN + tid];
            s = __fadd_rn(s, __fmul_rn(v, v));
        }
        szsq[tid] = s;
    }
    __syncthreads();

    const int r0 = ty * 8;                  // this thread's 8 rows
    const int c0 = tx * 8;                  // this thread's 8 codes (within chunk)
    float zs[8];
    #pragma unroll
    for (int q = 0; q < 8; q++) zs[q] = szsq[r0 + q];

    const float INFF = __int_as_float(0x7f800000);
    float bd[8]; int bi[8];
    #pragma unroll
    for (int q = 0; q < 8; q++) { bd[q] = INFF; bi[q] = 0; }

    const float* cbg0 = cbk + (size_t)m * N_E * E_DIM;

    for (int ch = 0; ch < 8; ch++) {
        __syncthreads();
        // load + transpose codebook chunk: codes [ch*128, ch*128+128)
        const float* cg = cbg0 + (size_t)(ch * TC) * E_DIM;
        #pragma unroll
        for (int it = 0; it < 8; it++) {
            int i = tid + it * 256;          // 0..2047 float4 slots
            int code = i >> 4, k4 = (i & 15) * 4;
            float4 v = *(const float4*)(cg + (size_t)code * E_DIM + k4);
            scb[(k4 + 0) * CBS + code] = v.x;
            scb[(k4 + 1) * CBS + code] = v.y;
            scb[(k4 + 2) * CBS + code] = v.z;
            scb[(k4 + 3) * CBS + code] = v.w;
        }
        __syncthreads();

        // 8x8 register tile, rows packed in pairs -> 32 packed FMA per k
        unsigned long long acc[4][8];
        #pragma unroll
        for (int p = 0; p < 4; p++)
            #pragma unroll
            for (int j = 0; j < 8; j++) acc[p][j] = 0ull;   // (0.0f, 0.0f)

        #pragma unroll 4
        for (int k = 0; k < E_DIM; k++) {
            const float4 za  = *(const float4*)(szt + k * TN + r0);
            const float4 zb  = *(const float4*)(szt + k * TN + r0 + 4);
            const float4 ca  = *(const float4*)(scb + k * CBS + c0);
            const float4 cb4 = *(const float4*)(scb + k * CBS + c0 + 4);
            unsigned long long zp0 = pk2(za.x, za.y);
            unsigned long long zp1 = pk2(za.z, za.w);
            unsigned long long zp2 = pk2(zb.x, zb.y);
            unsigned long long zp3 = pk2(zb.z, zb.w);
            float cj[8] = {ca.x, ca.y, ca.z, ca.w, cb4.x, cb4.y, cb4.z, cb4.w};
            #pragma unroll
            for (int j = 0; j < 8; j++) {
                unsigned long long bb = pk2(cj[j], cj[j]);
                acc[0][j] = fma2(zp0, bb, acc[0][j]);
                acc[1][j] = fma2(zp1, bb, acc[1][j]);
                acc[2][j] = fma2(zp2, bb, acc[2][j]);
                acc[3][j] = fma2(zp3, bb, acc[3][j]);
            }
        }

        // epilogue: d = fl( fl(zsq + esq) - 2*dot ), strict-less keeps lowest idx
        #pragma unroll
        for (int j = 0; j < 8; j++) {
            int c = ch * TC + c0 + j;
            float ev = sesq[c];
            #pragma unroll
            for (int p = 0; p < 4; p++) {
                float alo, ahi; upk2(acc[p][j], alo, ahi);
                float t0 = __fadd_rn(zs[2 * p], ev);
                float d0 = __fsub_rn(t0, __fmul_rn(2.0f, alo));
                if (d0 < bd[2 * p]) { bd[2 * p] = d0; bi[2 * p] = c; }
                float t1 = __fadd_rn(zs[2 * p + 1], ev);
                float d1 = __fsub_rn(t1, __fmul_rn(2.0f, ahi));
                if (d1 < bd[2 * p + 1]) { bd[2 * p + 1] = d1; bi[2 * p + 1] = c; }
            }
        }
    }

    // cross-thread (tx) reduction with lexicographic (d, idx) tie-breaking
    __syncthreads();
    float* rd = scb;                 // 128*16 floats
    int*   ri = (int*)(scb + 2048);  // 128*16 ints
    #pragma unroll
    for (int q = 0; q < 8; q++) {
        rd[(r0 + q) * 16 + tx] = bd[q];
        ri[(r0 + q) * 16 + tx] = bi[q];
    }
    __syncthreads();
    if (tid < TN) {
        float best = rd[tid * 16]; int besti = ri[tid * 16];
        #pragma unroll
        for (int t = 1; t < 16; t++) {
            float dv = rd[tid * 16 + t]; int iv = ri[tid * 16 + t];
            if (dv < best || (dv == best && iv < besti)) { best = dv; besti = iv; }
        }
        int n = n0 + tid;
        g_idx[m * NPOS + n] = besti;
        outIdx[m * NPOS + n] = (float)besti;
        atomicAdd(outBins + besti, 1.0f);   // integer-valued float adds: exact
    }
}

// ---------------- K2: gather z_vq + loss partial sums ------------------------
// One float4 per thread along w. grid = 8192 x 256.
__global__ void pq_gather_kernel(const float* __restrict__ z,
                                 const float* __restrict__ cbk,
                                 float* __restrict__ outZvq)
{
    __shared__ double swarp[8];
    int e4 = blockIdx.x * blockDim.x + threadIdx.x;   // 0 .. 2,097,151
    int w4 = e4 & 7;
    int t1 = e4 >> 3;
    int h  = t1 & 31;
    int t2 = t1 >> 5;
    int chn = t2 & 511;
    int b  = t2 >> 9;
    int m  = chn >> 6;
    int d  = chn & 63;
    int nb = b * HW_ + h * WW_ + w4 * 4;

    float4 zf4 = *(const float4*)(z + (size_t)e4 * 4);
    float zf[4] = {zf4.x, zf4.y, zf4.z, zf4.w};
    float ov[4];
    double lsum = 0.0;
    #pragma unroll
    for (int q = 0; q < 4; q++) {
        int idx = g_idx[m * NPOS + nb + q];
        float zq = cbk[((size_t)m * N_E + idx) * E_DIM + d];
        float df = __fsub_rn(zq, zf[q]);                 // zq - zf
        ov[q] = __fadd_rn(zf[q], df);                    // zf + (zq - zf)
        lsum += (double)df * (double)df;
    }
    *(float4*)(outZvq + (size_t)e4 * 4) = make_float4(ov[0], ov[1], ov[2], ov[3]);

    // deterministic per-block reduction -> g_part[blockIdx.x]
    #pragma unroll
    for (int off = 16; off > 0; off >>= 1)
        lsum += __shfl_down_sync(0xffffffffu, lsum, off);
    int lane = threadIdx.x & 31, wid = threadIdx.x >> 5;
    if (lane == 0) swarp[wid] = lsum;
    __syncthreads();
    if (wid == 0) {
        double v = (lane < 8) ? swarp[lane] : 0.0;
        #pragma unroll
        for (int off = 4; off > 0; off >>= 1)
            v += __shfl_down_sync(0xffffffffu, v, off);
        if (lane == 0) g_part[blockIdx.x] = v;
    }
}

// ---------------- K3: finalize loss (deterministic fixed-order sum) ----------
__global__ void pq_loss_kernel(float* __restrict__ outLoss) {
    __shared__ double sred[256];
    int t = threadIdx.x;
    double s = 0.0;
    for (int i = t; i < 8192; i += 256) s += g_part[i];
    sred[t] = s;
    __syncthreads();
    for (int off = 128; off > 0; off >>= 1) {
        if (t < off) sred[t] += sred[t + off];
        __syncthreads();
    }
    if (t == 0) {
        // loss = sum_m (1+beta) * mean_m = 1.25 * total / (NPOS*E_DIM)
        double loss = 1.25 * sred[0] / (double)((size_t)NPOS * E_DIM);
        outLoss[0] = (float)loss;
    }
}

// ---------------- launch ------------------------------------------------------
extern "C" void kernel_launch(void* const* d_in, const int* in_sizes, int n_in,
                              void* d_out, int out_size)
{
    const float* z   = (const float*)d_in[0];
    const float* cbk = (const float*)d_in[1];
    if (n_in >= 2 && in_sizes[0] == M_SUB * N_E * E_DIM) {  // swapped order safety
        z   = (const float*)d_in[1];
        cbk = (const float*)d_in[0];
    }
    float* out = (float*)d_out;
    float* outZvq  = out + OFF_ZVQ;
    float* outLoss = out + OFF_LOSS;
    float* outIdx  = out + OFF_IDX;
    float* outBins = out + OFF_BIN;

    const int dyn_smem = (8192 + 64 * CBS + 1024 + 128) * 4;  // 71168 B
    cudaFuncSetAttribute(pq_dist_kernel,
                         cudaFuncAttributeMaxDynamicSharedMemorySize, dyn_smem);

    pq_init_kernel<<<1, 1024>>>(outBins);
    pq_esq_kernel<<<(M_SUB * N_E + 255) / 256, 256>>>(cbk);
    dim3 g1(NPOS / TN, M_SUB);
    pq_dist_kernel<<<g1, 256, dyn_smem>>>(z, cbk, outIdx, outBins);
    pq_gather_kernel<<<8192, 256>>>(z, cbk, outZvq);
    pq_loss_kernel<<<1, 256>>>(outLoss);
}

// round 5
// speedup vs baseline: 1.0377x; 1.0377x over previous
#include <cuda_runtime.h>
#include <cstdint>

// Problem constants
#define M_SUB   8
#define N_E     1024
#define E_DIM   64
#define BS_     16
#define CC_     512
#define HW_     1024
#define NPOS    16384            // BS_*HW_

// Output layout (float32)
#define OFF_ZVQ  0
#define OFF_LOSS 8388608
#define OFF_IDX  8388609
#define OFF_BIN  8519681

// Scratch (device globals; no allocation allowed)
__device__ float  g_esq[M_SUB * N_E];
__device__ float  g_cbt[M_SUB * E_DIM * N_E];   // transposed codebooks [m][k][code]
__device__ double g_part[1024];

// ---------------- f32x2 packed FMA helpers -----------------------------------
__device__ __forceinline__ void upk2(unsigned long long v, float& lo, float& hi) {
    asm("mov.b64 {%0, %1}, %2;" : "=f"(lo), "=f"(hi) : "l"(v));
}
__device__ __forceinline__ unsigned long long fma2(unsigned long long a,
                                                   unsigned long long b,
                                                   unsigned long long c) {
    unsigned long long d;
    asm("fma.rn.f32x2 %0, %1, %2, %3;" : "=l"(d) : "l"(a), "l"(b), "l"(c));
    return d;
}

// ---------------- K0: zero bins -----------------------------------------------
__global__ void pq_init_kernel(float* __restrict__ outBins) {
    int t = threadIdx.x;
    if (t < N_E) outBins[t] = 0.0f;
}

// ---------------- K_esq: per-code squared norms (mul then sequential add) -----
__global__ void pq_esq_kernel(const float* __restrict__ cbk) {
    int t = blockIdx.x * blockDim.x + threadIdx.x;   // 0..8191
    if (t >= M_SUB * N_E) return;
    const float* p = cbk + (size_t)t * E_DIM;
    float s = 0.0f;
    #pragma unroll
    for (int d = 0; d < E_DIM; d++) {
        float v = p[d];
        s = __fadd_rn(s, __fmul_rn(v, v));
    }
    g_esq[t] = s;
}

// ---------------- K_tr: transpose codebooks to k-major ------------------------
// grid = 64 blocks (8 m x 8 code-tiles of 128), 256 threads
__global__ void pq_tr_kernel(const float* __restrict__ cbk) {
    __shared__ float st[64 * 128];
    int m  = blockIdx.x >> 3;
    int ct = (blockIdx.x & 7) * 128;
    int tid = threadIdx.x;
    int code = tid >> 1;             // 0..127
    int kh = (tid & 1) * 32;         // 0 or 32
    const float* src = cbk + ((size_t)(m * N_E) + ct + code) * E_DIM + kh;
    #pragma unroll
    for (int q = 0; q < 8; q++) {
        float4 v = *(const float4*)(src + q * 4);
        st[(kh + q * 4 + 0) * 128 + code] = v.x;
        st[(kh + q * 4 + 1) * 128 + code] = v.y;
        st[(kh + q * 4 + 2) * 128 + code] = v.z;
        st[(kh + q * 4 + 3) * 128 + code] = v.w;
    }
    __syncthreads();
    float* dst = g_cbt + (size_t)m * E_DIM * N_E + ct;
    #pragma unroll
    for (int it = 0; it < 8; it++) {
        int i = tid + it * 256;
        int k = i >> 5, c4 = (i & 31) * 4;
        *(float4*)(dst + (size_t)k * N_E + c4) = *(const float4*)(st + k * 128 + c4);
    }
}

// ---------------- K1: distances + argmin + fused z_vq/loss --------------------
// Block 256 threads. Tile: 128 rows x 1024 codes (8 chunks of 128).
// grid = (128 row-tiles, 8 sub-codebooks)
#define TN 128

__global__ void __launch_bounds__(256, 2)
pq_dist_kernel(const float* __restrict__ z,
               const float* __restrict__ cbk,
               float* __restrict__ outZvq,
               float* __restrict__ outIdx,
               float* __restrict__ outBins)
{
    extern __shared__ float sm[];
    float* szt  = sm;                        // 64*256 = 16384 (z tile, duplicated pairs)
    float* scb  = sm + 16384;                // 64*128 = 8192 (codebook chunk, k-major)
    float* sesq = scb + 8192;                // 1024
    float* szsq = sesq + 1024;               // 128
    int*   swin = (int*)(szsq + 128);        // 128
    // total 25856 floats = 103424 B

    __shared__ double swarp[8];

    const int m  = blockIdx.y;
    const int n0 = blockIdx.x * TN;
    const int b  = n0 >> 10;
    const int p0 = n0 & 1023;
    const int tid = threadIdx.x;
    const int tx = tid & 15, ty = tid >> 4;

    // Load z tile (channels [m*64, m*64+64), positions [p0, p0+128)), duplicated:
    // szt[k][2*j] = szt[k][2*j+1] = z[k][j]
    const float* zbase = z + ((size_t)(b * CC_ + m * E_DIM) * HW_) + p0;
    #pragma unroll
    for (int it = 0; it < 8; it++) {
        int i = tid + it * 256;
        int d = i >> 5, j4 = (i & 31) * 4;
        float4 v = *(const float4*)(zbase + (size_t)d * HW_ + j4);
        float* dst = szt + d * 256 + 2 * j4;
        *(float4*)(dst)     = make_float4(v.x, v.x, v.y, v.y);
        *(float4*)(dst + 4) = make_float4(v.z, v.z, v.w, v.w);
    }
    #pragma unroll
    for (int it = 0; it < 4; it++)
        sesq[tid + it * 256] = g_esq[m * N_E + tid + it * 256];
    __syncthreads();

    // per-row ||z||^2: square rounded, then sequential add
    if (tid < TN) {
        float s = 0.0f;
        #pragma unroll
        for (int k = 0; k < E_DIM; k++) {
            float v = szt[k * 256 + 2 * tid];
            s = __fadd_rn(s, __fmul_rn(v, v));
        }
        szsq[tid] = s;
    }
    __syncthreads();

    const int r0 = ty * 8;       // thread's 8 rows
    const int c0 = tx * 4;       // thread's codes: {c0..c0+3, 64+c0..64+c0+3} per chunk
    float zs[8];
    #pragma unroll
    for (int q = 0; q < 8; q++) zs[q] = szsq[r0 + q];

    const float INFF = __int_as_float(0x7f800000);
    float bd[8]; int bi[8];
    #pragma unroll
    for (int q = 0; q < 8; q++) { bd[q] = INFF; bi[q] = 0; }

    const float* ctb = g_cbt + (size_t)m * (E_DIM * N_E);

    for (int ch = 0; ch < 8; ch++) {
        __syncthreads();
        // fill codebook chunk (already k-major in gmem): 2048 float4
        #pragma unroll
        for (int it = 0; it < 8; it++) {
            int i = tid + it * 256;
            int k = i >> 5, c4 = (i & 31) * 4;
            float4 v = *(const float4*)(ctb + (size_t)k * N_E + ch * 128 + c4);
            *(float4*)(scb + k * 128 + c4) = v;
        }
        __syncthreads();

        unsigned long long acc[8][4];
        #pragma unroll
        for (int r = 0; r < 8; r++)
            #pragma unroll
            for (int j = 0; j < 4; j++) acc[r][j] = 0ull;

        #pragma unroll 4
        for (int k = 0; k < E_DIM; k++) {
            const float* zr = szt + k * 256 + 2 * r0;
            ulonglong2 za = *(const ulonglong2*)(zr);        // rows r0,r0+1 dup
            ulonglong2 zb = *(const ulonglong2*)(zr + 4);    // r0+2,r0+3
            ulonglong2 zc = *(const ulonglong2*)(zr + 8);
            ulonglong2 zd = *(const ulonglong2*)(zr + 12);
            const float* cr = scb + k * 128 + c0;
            ulonglong2 ca = *(const ulonglong2*)(cr);        // codes (c0,c0+1),(c0+2,c0+3)
            ulonglong2 cb = *(const ulonglong2*)(cr + 64);   // codes 64+c0 ...
            unsigned long long zp[8] = {za.x, za.y, zb.x, zb.y, zc.x, zc.y, zd.x, zd.y};
            unsigned long long cp[4] = {ca.x, ca.y, cb.x, cb.y};
            #pragma unroll
            for (int r = 0; r < 8; r++)
                #pragma unroll
                for (int j = 0; j < 4; j++)
                    acc[r][j] = fma2(zp[r], cp[j], acc[r][j]);
        }

        // epilogue: d = fl( fl(zsq+esq) - 2*dot ); strict-less keeps lowest idx.
        // j ascending visits this thread's codes in increasing order.
        #pragma unroll
        for (int j = 0; j < 4; j++) {
            int cbase = ch * 128 + ((j < 2) ? (c0 + 2 * j) : (64 + c0 + 2 * (j - 2)));
            float e0 = sesq[cbase], e1 = sesq[cbase + 1];
            #pragma unroll
            for (int r = 0; r < 8; r++) {
                float alo, ahi; upk2(acc[r][j], alo, ahi);
                float d0 = __fsub_rn(__fadd_rn(zs[r], e0), __fmul_rn(2.0f, alo));
                if (d0 < bd[r]) { bd[r] = d0; bi[r] = cbase; }
                float d1 = __fsub_rn(__fadd_rn(zs[r], e1), __fmul_rn(2.0f, ahi));
                if (d1 < bd[r]) { bd[r] = d1; bi[r] = cbase + 1; }
            }
        }
    }

    // cross-thread (tx) reduction with lexicographic (d, idx) tie-breaking
    __syncthreads();
    float* rd = scb;                  // 128*16 floats
    int*   ri = (int*)(scb + 2048);   // 128*16 ints
    #pragma unroll
    for (int q = 0; q < 8; q++) {
        rd[(r0 + q) * 16 + tx] = bd[q];
        ri[(r0 + q) * 16 + tx] = bi[q];
    }
    __syncthreads();
    if (tid < TN) {
        float best = rd[tid * 16]; int besti = ri[tid * 16];
        #pragma unroll
        for (int t = 1; t < 16; t++) {
            float dv = rd[tid * 16 + t]; int iv = ri[tid * 16 + t];
            if (dv < best || (dv == best && iv < besti)) { best = dv; besti = iv; }
        }
        swin[tid] = besti;
        outIdx[m * NPOS + n0 + tid] = (float)besti;
        atomicAdd(outBins + besti, 1.0f);   // integer-valued float adds: exact
    }
    __syncthreads();

    // ---- fused gather: stage winning code rows into sq[row][d], stride 65 ----
    float* sq = scb;   // 128*65 = 8320 floats; fits in scb(8192)+sesq(1024)
    const float* cbm = cbk + (size_t)m * N_E * E_DIM;
    #pragma unroll
    for (int it = 0; it < 8; it++) {
        int i = tid + it * 256;          // 0..2047
        int row = i >> 4, d4 = (i & 15) * 4;
        int idx = swin[row];
        float4 v = *(const float4*)(cbm + (size_t)idx * E_DIM + d4);
        float* dp = sq + row * 65 + d4;
        dp[0] = v.x; dp[1] = v.y; dp[2] = v.z; dp[3] = v.w;
    }
    __syncthreads();

    // ---- write z_vq = zf + (zq - zf), accumulate loss partial in double ----
    double lsum = 0.0;
    float* ob = outZvq + ((size_t)(b * CC_ + m * E_DIM)) * HW_ + p0;
    #pragma unroll
    for (int it = 0; it < 8; it++) {
        int i = tid + it * 256;
        int d = i >> 5, j4 = (i & 31) * 4;
        float o[4];
        #pragma unroll
        for (int q = 0; q < 4; q++) {
            float zf = szt[d * 256 + 2 * (j4 + q)];
            float zq = sq[(j4 + q) * 65 + d];
            float df = __fsub_rn(zq, zf);
            o[q] = __fadd_rn(zf, df);
            lsum += (double)df * (double)df;
        }
        *(float4*)(ob + (size_t)d * HW_ + j4) = make_float4(o[0], o[1], o[2], o[3]);
    }

    // deterministic per-block reduction -> g_part[m*128 + blockIdx.x]
    #pragma unroll
    for (int off = 16; off > 0; off >>= 1)
        lsum += __shfl_down_sync(0xffffffffu, lsum, off);
    int lane = tid & 31, wid = tid >> 5;
    if (lane == 0) swarp[wid] = lsum;
    __syncthreads();
    if (wid == 0) {
        double v = (lane < 8) ? swarp[lane] : 0.0;
        #pragma unroll
        for (int off = 4; off > 0; off >>= 1)
            v += __shfl_down_sync(0xffffffffu, v, off);
        if (lane == 0) g_part[m * 128 + blockIdx.x] = v;
    }
}

// ---------------- K3: finalize loss (deterministic fixed-order sum) -----------
__global__ void pq_loss_kernel(float* __restrict__ outLoss) {
    __shared__ double sred[256];
    int t = threadIdx.x;
    double s = 0.0;
    for (int i = t; i < 1024; i += 256) s += g_part[i];
    sred[t] = s;
    __syncthreads();
    for (int off = 128; off > 0; off >>= 1) {
        if (t < off) sred[t] += sred[t + off];
        __syncthreads();
    }
    if (t == 0) {
        double loss = 1.25 * sred[0] / (double)((size_t)NPOS * E_DIM);
        outLoss[0] = (float)loss;
    }
}

// ---------------- launch -------------------------------------------------------
extern "C" void kernel_launch(void* const* d_in, const int* in_sizes, int n_in,
                              void* d_out, int out_size)
{
    const float* z   = (const float*)d_in[0];
    const float* cbk = (const float*)d_in[1];
    if (n_in >= 2 && in_sizes[0] == M_SUB * N_E * E_DIM) {  // swapped-order safety
        z   = (const float*)d_in[1];
        cbk = (const float*)d_in[0];
    }
    float* out = (float*)d_out;
    float* outZvq  = out + OFF_ZVQ;
    float* outLoss = out + OFF_LOSS;
    float* outIdx  = out + OFF_IDX;
    float* outBins = out + OFF_BIN;

    const int dyn_smem = 25856 * 4;   // 103424 B
    cudaFuncSetAttribute(pq_dist_kernel,
                         cudaFuncAttributeMaxDynamicSharedMemorySize, dyn_smem);

    pq_init_kernel<<<1, 1024>>>(outBins);
    pq_esq_kernel<<<(M_SUB * N_E + 255) / 256, 256>>>(cbk);
    pq_tr_kernel<<<64, 256>>>(cbk);
    dim3 g1(NPOS / TN, M_SUB);
    pq_dist_kernel<<<g1, 256, dyn_smem>>>(z, cbk, outZvq, outIdx, outBins);
    pq_loss_kernel<<<1, 256>>>(outLoss);
}